// round 16
// baseline (speedup 1.0000x reference)
#include <cuda_runtime.h>

// ---------------------------------------------------------------------------
// SpatialRangeAttention — GB300 sm_103a
// ---------------------------------------------------------------------------

#define BB   2
#define CC   64
#define HH   112
#define WW   112
#define HWP  (HH*WW)      // 12544
#define NPIX (BB*HWP)     // 25088
#define N2   49

// Scratch
__device__ float g_spa_t[NPIX*CC];   // spatial transposed [pix][c]
__device__ float g_px_cm[NPIX*CC];   // range-projected, CHANNEL-major [b][c][hw]
__device__ float g_nrm[NPIX];        // per-pixel ||px||^2
__device__ float g_comb[NPIX*N2];    // bilateral / final weights [pix][n]

// Interleaved weight buffers (shared by all blocks; L1/L2-resident)
__device__ float2 g_w1r[64*32], g_w2r[64*32];   // range
__device__ float2 g_w1f[113*32], g_w2f[49*32];  // fixup (zero-padded o>=49)
__device__ float2 g_w1o[64*32], g_w2o[64*32];   // output

// 8-FMA block: weight pair times 4 pixel x-values
#define ACC8(a, xa)                                   \
    y0[0]+=a.x*xa.x; y1[0]+=a.y*xa.x;                 \
    y0[1]+=a.x*xa.y; y1[1]+=a.y*xa.y;                 \
    y0[2]+=a.x*xa.z; y1[2]+=a.y*xa.z;                 \
    y0[3]+=a.x*xa.w; y1[3]+=a.y*xa.w;

// ---------------------------------------------------------------------------
// K-1: prep — interleave all conv weights into global float2 buffers
// ---------------------------------------------------------------------------
__global__ __launch_bounds__(256) void k_prep(
    const float* __restrict__ rw1, const float* __restrict__ rw2,
    const float* __restrict__ fw1, const float* __restrict__ fw2,
    const float* __restrict__ ow1, const float* __restrict__ ow2)
{
    int i = blockIdx.x * 256 + threadIdx.x;
    if (i < 2048) {
        int c = i >> 5, l = i & 31;
        g_w1r[i] = make_float2(rw1[l*64 + c], rw1[(l+32)*64 + c]);
        g_w2r[i] = make_float2(rw2[l*64 + c], rw2[(l+32)*64 + c]);
        g_w1o[i] = make_float2(ow1[l*64 + c], ow1[(l+32)*64 + c]);
        g_w2o[i] = make_float2(ow2[l*64 + c], ow2[(l+32)*64 + c]);
    }
    if (i < 113*32) {
        int j = i >> 5, l = i & 31;
        g_w1f[i] = make_float2((l    < N2) ? fw1[l*113 + j]      : 0.f,
                               (l+32 < N2) ? fw1[(l+32)*113 + j] : 0.f);
    }
    if (i < 49*32) {
        int j = i >> 5, l = i & 31;
        g_w2f[i] = make_float2((l    < N2) ? fw2[l*49 + j]      : 0.f,
                               (l+32 < N2) ? fw2[(l+32)*49 + j] : 0.f);
    }
}

// ---------------------------------------------------------------------------
// K0: transpose spatial input [B,C,HW] -> [B*HW, C]
// ---------------------------------------------------------------------------
__global__ __launch_bounds__(256) void k_transpose(const float* __restrict__ spa)
{
    __shared__ float t1[32][33];
    int b  = blockIdx.z;
    int c0 = blockIdx.y * 32;
    int p0 = blockIdx.x * 32;
    int tx = threadIdx.x, ty = threadIdx.y;
    #pragma unroll
    for (int i = ty; i < 32; i += 8)
        t1[i][tx] = spa[(b*CC + c0 + i)*HWP + p0 + tx];
    __syncthreads();
    #pragma unroll
    for (int i = ty; i < 32; i += 8)
        g_spa_t[(b*HWP + p0 + i)*CC + c0 + tx] = t1[tx][i];
}

// ---------------------------------------------------------------------------
// K1: range_proj. 4 px/warp, 8 accumulators, weights via LDG.
// 128 threads, grid NPIX/16 = 1568 -> ~42 warps/SM.
// ---------------------------------------------------------------------------
__global__ __launch_bounds__(128, 10) void k_range(
    const float* __restrict__ sem,
    const float* __restrict__ b1, const float* __restrict__ g,
    const float* __restrict__ be, const float* __restrict__ b2)
{
    extern __shared__ float sm[];
    float* xs = sm;                          // [4 warps][64 rows][4 px]
    int tid = threadIdx.x, lane = tid & 31, w = tid >> 5;

    float b1_0 = b1[lane], b1_1 = b1[lane+32];
    float g_0  = g[lane],  g_1  = g[lane+32];
    float be_0 = be[lane], be_1 = be[lane+32];
    float b2_0 = b2[lane], b2_1 = b2[lane+32];

    int pbase = blockIdx.x * 16 + w * 4;
    int bI = pbase / HWP, ppb = pbase % HWP;
    float* xw = xs + w * 256;

    // stage 4 pixels from channel-major sem: lane = (q = lane&3, grp = lane>>2)
    {
        int q = lane & 3, grp = lane >> 2;
        const float* semb = sem + (size_t)bI*CC*HWP + ppb + q;
        #pragma unroll 4
        for (int i = 0; i < 8; i++) {
            int c = grp*8 + i;
            xw[c*4 + q] = semb[(size_t)c*HWP];
        }
    }
    __syncwarp();

    float y0[4], y1[4];
    #pragma unroll
    for (int q = 0; q < 4; q++) { y0[q] = b1_0; y1[q] = b1_1; }

    #pragma unroll 4
    for (int c = 0; c < 64; c++) {
        float2 a = __ldg(&g_w1r[c*32 + lane]);
        float4 xa = *(const float4*)(xw + c*4);
        ACC8(a, xa)
    }

    {
        float h0[4], h1[4];
        #pragma unroll
        for (int q = 0; q < 4; q++) {
            float s = y0[q] + y1[q];
            float t = y0[q]*y0[q] + y1[q]*y1[q];
            #pragma unroll
            for (int o = 16; o; o >>= 1) {
                s += __shfl_xor_sync(0xffffffffu, s, o);
                t += __shfl_xor_sync(0xffffffffu, t, o);
            }
            float mean = s * (1.f/64.f);
            float rstd = rsqrtf(t * (1.f/64.f) - mean*mean + 1e-6f);
            float a0 = g_0 * (y0[q]-mean) * rstd + be_0;
            float a1 = g_1 * (y1[q]-mean) * rstd + be_1;
            h0[q] = a0 / (1.f + __expf(-a0));
            h1[q] = a1 / (1.f + __expf(-a1));
        }
        __syncwarp();
        *(float4*)&xw[lane*4]      = make_float4(h0[0],h0[1],h0[2],h0[3]);
        *(float4*)&xw[(lane+32)*4] = make_float4(h1[0],h1[1],h1[2],h1[3]);
        __syncwarp();
    }

    #pragma unroll
    for (int q = 0; q < 4; q++) { y0[q] = b2_0; y1[q] = b2_1; }
    #pragma unroll 4
    for (int c = 0; c < 64; c++) {
        float2 a = __ldg(&g_w2r[c*32 + lane]);
        float4 xa = *(const float4*)(xw + c*4);
        ACC8(a, xa)
    }

    #pragma unroll
    for (int q = 0; q < 4; q++) {
        float t = y0[q]*y0[q] + y1[q]*y1[q];
        #pragma unroll
        for (int o = 16; o; o >>= 1) t += __shfl_xor_sync(0xffffffffu, t, o);
        if (lane == 0) g_nrm[pbase + q] = t;
    }
    {
        float* d0 = &g_px_cm[(size_t)(bI*CC + lane)*HWP + ppb];
        *(float4*)d0 = make_float4(y0[0],y0[1],y0[2],y0[3]);
        float* d1 = &g_px_cm[(size_t)(bI*CC + lane + 32)*HWP + ppb];
        *(float4*)d1 = make_float4(y1[0],y1[1],y1[2],y1[3]);
    }
}

// ---------------------------------------------------------------------------
// K2: bilateral (R9-exact): dist2 = |n|^2+|c|^2-2dot. Warp = (32 pixels, dy).
// ---------------------------------------------------------------------------
__global__ __launch_bounds__(256) void k_bilateral(const float* __restrict__ sigma)
{
    int wid  = (blockIdx.x << 3) + (threadIdx.x >> 5);
    int lane = threadIdx.x & 31;
    int gpix = wid / 7;
    int dyi  = wid - gpix*7;
    int dy   = dyi - 3;

    int p  = (gpix << 5) + lane;
    int b  = p / HWP, pp = p % HWP, yy = pp / WW, xx = pp % WW;
    int ny = yy + dy;
    bool rowok = ((unsigned)ny < HH);
    int nrow = (rowok ? ny : yy) * WW;

    const float* base = g_px_cm + (size_t)b * (CC*HWP);

    int off[7]; unsigned okm = 0;
    #pragma unroll
    for (int i = 0; i < 7; i++) {
        int nx = xx + i - 3;
        bool o = rowok & ((unsigned)nx < WW);
        okm |= (o ? 1u : 0u) << i;
        off[i] = nrow + (o ? nx : xx);
    }

    float acc[7] = {0.f,0.f,0.f,0.f,0.f,0.f,0.f};
    #pragma unroll 4
    for (int c = 0; c < CC; c++) {
        const float* rc = base + c*HWP;
        float cv = rc[pp];
        #pragma unroll
        for (int i = 0; i < 7; i++) acc[i] += cv * rc[off[i]];
    }

    float nc = g_nrm[p];
    float sg = *sigma;
    float is2 = 0.5f / (sg*sg);
    float* outp = &g_comb[(size_t)p*N2 + dyi*7];
    const float* nrmb = &g_nrm[b*HWP];
    #pragma unroll
    for (int i = 0; i < 7; i++) {
        float res = 0.f;
        if ((okm >> i) & 1u) {
            float d2 = fmaxf(nrmb[off[i]] + nc - 2.f*acc[i], 0.f);
            float fdx = (float)(i - 3);
            res = __expf(-d2*(1.f/128.f) - ((float)(dy*dy) + fdx*fdx)*is2);
        }
        outp[i] = res;
    }
}

// ---------------------------------------------------------------------------
// K3a: fixup. 4 px/warp, 8 accumulators, weights via LDG.
// 128 threads, grid NPIX/16 = 1568 -> ~42 warps/SM. smem 7232B/block.
// ---------------------------------------------------------------------------
__global__ __launch_bounds__(128, 10) void k_fixup(
    const float* __restrict__ sem,
    const float* __restrict__ b1, const float* __restrict__ g,
    const float* __restrict__ be, const float* __restrict__ b2)
{
    extern __shared__ float sm[];
    float* xs = sm;                          // [4 warps][113][4]
    int tid = threadIdx.x, lane = tid & 31, w = tid >> 5;

    const bool has2 = (lane + 32) < N2;
    float b1_0 = (lane < N2) ? b1[lane] : 0.f;
    float b1_1 = has2 ? b1[lane+32] : 0.f;
    float g_0  = (lane < N2) ? g[lane]  : 0.f;
    float g_1  = has2 ? g[lane+32]  : 0.f;
    float be_0 = (lane < N2) ? be[lane] : 0.f;
    float be_1 = has2 ? be[lane+32] : 0.f;
    float b2_0 = (lane < N2) ? b2[lane] : 0.f;
    float b2_1 = has2 ? b2[lane+32] : 0.f;

    int pbase = blockIdx.x * 16 + w * 4;
    int bI = pbase / HWP, ppb = pbase % HWP;
    float* xw = xs + w * 452;

    // stage: lane = (q = lane&3, grp = lane>>2); 8 grps cover j in chunks of 15
    {
        int q = lane & 3, grp = lane >> 2;
        const float* combp = g_comb + (size_t)(pbase + q)*N2;
        const float* semb  = sem + (size_t)bI*CC*HWP + ppb + q;
        int j0 = grp * 15;
        int j1 = (grp == 7) ? 113 : j0 + 15;
        for (int j = j0; j < j1; j++) {
            float v = (j < N2) ? combp[j] : semb[(size_t)(j - N2)*HWP];
            xw[j*4 + q] = v;
        }
    }
    __syncwarp();

    float y0[4], y1[4];
    #pragma unroll
    for (int q = 0; q < 4; q++) { y0[q] = b1_0; y1[q] = b1_1; }

    #pragma unroll 4
    for (int j = 0; j < 113; j++) {
        float2 a = __ldg(&g_w1f[j*32 + lane]);
        float4 xa = *(const float4*)(xw + j*4);
        ACC8(a, xa)
    }

    {
        float h0[4], h1[4];
        #pragma unroll
        for (int q = 0; q < 4; q++) {
            float s = y0[q] + (has2 ? y1[q] : 0.f);
            float t = y0[q]*y0[q] + (has2 ? y1[q]*y1[q] : 0.f);
            #pragma unroll
            for (int o = 16; o; o >>= 1) {
                s += __shfl_xor_sync(0xffffffffu, s, o);
                t += __shfl_xor_sync(0xffffffffu, t, o);
            }
            float mean = s * (1.f/49.f);
            float rstd = rsqrtf(t * (1.f/49.f) - mean*mean + 1e-6f);
            float a0 = g_0 * (y0[q]-mean) * rstd + be_0;
            float a1 = g_1 * (y1[q]-mean) * rstd + be_1;
            h0[q] = a0 / (1.f + __expf(-a0));
            h1[q] = a1 / (1.f + __expf(-a1));
        }
        __syncwarp();
        *(float4*)&xw[lane*4] = make_float4(h0[0],h0[1],h0[2],h0[3]);
        if (has2)
            *(float4*)&xw[(lane+32)*4] = make_float4(h1[0],h1[1],h1[2],h1[3]);
        __syncwarp();
    }

    #pragma unroll
    for (int q = 0; q < 4; q++) { y0[q] = b2_0; y1[q] = b2_1; }
    #pragma unroll 4
    for (int j = 0; j < 49; j++) {
        float2 a = __ldg(&g_w2f[j*32 + lane]);
        float4 xa = *(const float4*)(xw + j*4);
        ACC8(a, xa)
    }

    #pragma unroll
    for (int q = 0; q < 4; q++) {
        int p = pbase + q;
        float cb0 = g_comb[(size_t)p*N2 + lane];
        float cb1 = has2 ? g_comb[(size_t)p*N2 + lane + 32] : 0.f;
        float wv0 = cb0 * (1.f + 1.f/(1.f + __expf(-y0[q])));
        float wv1 = has2 ? cb1 * (1.f + 1.f/(1.f + __expf(-y1[q]))) : 0.f;
        float ss = wv0 + wv1;
        #pragma unroll
        for (int o = 16; o; o >>= 1) ss += __shfl_xor_sync(0xffffffffu, ss, o);
        float inv = 1.f / (ss + 1e-7f);
        g_comb[(size_t)p*N2 + lane] = wv0 * inv;
        if (has2) g_comb[(size_t)p*N2 + lane + 32] = wv1 * inv;
    }
}

// ---------------------------------------------------------------------------
// K3b: weighted neighborhood reduction + output_proj, weights via LDG.
// 4 px/warp, 128 threads, grid NPIX/16 = 1568. Interior fast path in gather.
// ---------------------------------------------------------------------------
__global__ __launch_bounds__(128, 10) void k_output(
    const float* __restrict__ b1, const float* __restrict__ g,
    const float* __restrict__ be, const float* __restrict__ b2,
    float* __restrict__ out)
{
    extern __shared__ float sm[];
    float* wsb = sm;                        // [4][52]
    float* os  = sm + 208;                  // [4 warps][64][4]
    int tid = threadIdx.x, lane = tid & 31, w = tid >> 5;

    float b1_0 = b1[lane], b1_1 = b1[lane+32];
    float g_0  = g[lane],  g_1  = g[lane+32];
    float be_0 = be[lane], be_1 = be[lane+32];
    float b2_0 = b2[lane], b2_1 = b2[lane+32];

    int pbase = blockIdx.x * 16 + w * 4;
    int bI = pbase / HWP, ppb = pbase % HWP;
    float* ow   = os  + w * 256;
    float* wrow = wsb + w * 52;

    // Gather: lane owns channels (2*lane, 2*lane+1)
    {
        float a0[4], a1[4];
        #pragma unroll
        for (int q = 0; q < 4; q++) {
            int pp = ppb + q;
            int yy = pp / WW, xx = pp % WW;

            for (int n = lane; n < N2; n += 32) wrow[n] = g_comb[(size_t)(pbase+q)*N2 + n];
            __syncwarp();

            float s0 = 0.f, s1 = 0.f;
            if (yy >= 3 && yy < HH-3 && xx >= 3 && xx < WW-3) {
                // interior fast path: no clamps, pointer-walk
                const float* rp0 = &g_spa_t[(size_t)(bI*HWP + (yy-3)*WW + (xx-3))*CC + lane*2];
                int n = 0;
                #pragma unroll
                for (int dy = 0; dy < 7; dy++) {
                    const float* rp = rp0 + (size_t)dy*WW*CC;
                    #pragma unroll
                    for (int dx = 0; dx < 7; dx++, n++) {
                        float wv = wrow[n];
                        float2 sv = *(const float2*)(rp + dx*CC);
                        s0 += sv.x * wv;
                        s1 += sv.y * wv;
                    }
                }
            } else {
                int n = 0;
                #pragma unroll
                for (int dy = -3; dy <= 3; dy++) {
                    int ny = min(max(yy + dy, 0), HH-1);
                    const float* rbase = &g_spa_t[(size_t)(bI*HWP + ny*WW)*CC + lane*2];
                    #pragma unroll
                    for (int dx = -3; dx <= 3; dx++, n++) {
                        int nx = min(max(xx + dx, 0), WW-1);
                        float wv = wrow[n];              // 0 for OOB neighbors
                        float2 sv = *(const float2*)(rbase + nx*CC);
                        s0 += sv.x * wv;
                        s1 += sv.y * wv;
                    }
                }
            }
            a0[q] = s0; a1[q] = s1;
            __syncwarp();
        }
        *(float4*)&ow[(lane*2)*4]   = make_float4(a0[0],a0[1],a0[2],a0[3]);
        *(float4*)&ow[(lane*2+1)*4] = make_float4(a1[0],a1[1],a1[2],a1[3]);
        __syncwarp();
    }

    float y0[4], y1[4];
    #pragma unroll
    for (int q = 0; q < 4; q++) { y0[q] = b1_0; y1[q] = b1_1; }
    #pragma unroll 4
    for (int c = 0; c < 64; c++) {
        float2 a = __ldg(&g_w1o[c*32 + lane]);
        float4 xa = *(const float4*)(ow + c*4);
        ACC8(a, xa)
    }

    {
        float h0[4], h1[4];
        #pragma unroll
        for (int q = 0; q < 4; q++) {
            float s = y0[q] + y1[q];
            float t = y0[q]*y0[q] + y1[q]*y1[q];
            #pragma unroll
            for (int o = 16; o; o >>= 1) {
                s += __shfl_xor_sync(0xffffffffu, s, o);
                t += __shfl_xor_sync(0xffffffffu, t, o);
            }
            float mean = s * (1.f/64.f);
            float rstd = rsqrtf(t * (1.f/64.f) - mean*mean + 1e-6f);
            h0[q] = g_0 * (y0[q]-mean) * rstd + be_0;
            h1[q] = g_1 * (y1[q]-mean) * rstd + be_1;
        }
        __syncwarp();
        *(float4*)&ow[lane*4]      = make_float4(h0[0],h0[1],h0[2],h0[3]);
        *(float4*)&ow[(lane+32)*4] = make_float4(h1[0],h1[1],h1[2],h1[3]);
        __syncwarp();
    }

    #pragma unroll
    for (int q = 0; q < 4; q++) { y0[q] = b2_0; y1[q] = b2_1; }
    #pragma unroll 4
    for (int c = 0; c < 64; c++) {
        float2 a = __ldg(&g_w2o[c*32 + lane]);
        float4 xa = *(const float4*)(ow + c*4);
        ACC8(a, xa)
    }

    {
        float* d0 = &out[(size_t)(bI*CC + lane)*HWP + ppb];
        *(float4*)d0 = make_float4(y0[0],y0[1],y0[2],y0[3]);
        float* d1 = &out[(size_t)(bI*CC + lane + 32)*HWP + ppb];
        *(float4*)d1 = make_float4(y1[0],y1[1],y1[2],y1[3]);
    }
}

// ---------------------------------------------------------------------------
extern "C" void kernel_launch(void* const* d_in, const int* in_sizes, int n_in,
                              void* d_out, int out_size)
{
    const float* spa = (const float*)d_in[0];
    const float* sem = (const float*)d_in[1];

    static bool attr_set = false;
    if (!attr_set) {
        cudaFuncSetAttribute(k_range,  cudaFuncAttributeMaxDynamicSharedMemorySize, 4096);
        cudaFuncSetAttribute(k_fixup,  cudaFuncAttributeMaxDynamicSharedMemorySize, 7232);
        cudaFuncSetAttribute(k_output, cudaFuncAttributeMaxDynamicSharedMemorySize, 4928);
        attr_set = true;
    }

    k_prep<<<15, 256>>>((const float*)d_in[2], (const float*)d_in[6],
                        (const float*)d_in[8], (const float*)d_in[12],
                        (const float*)d_in[14], (const float*)d_in[18]);

    dim3 tg(HWP/32, CC/32, BB), tb(32, 8);
    k_transpose<<<tg, tb>>>(spa);

    k_range<<<NPIX/16, 128, 4096>>>(sem,
                                    (const float*)d_in[3],
                                    (const float*)d_in[4], (const float*)d_in[5],
                                    (const float*)d_in[7]);

    // warps = (NPIX/32) * 7 = 5488 ; 8 warps/block -> 686 blocks
    k_bilateral<<<686, 256>>>((const float*)d_in[20]);

    k_fixup<<<NPIX/16, 128, 7232>>>(sem,
                                    (const float*)d_in[9],
                                    (const float*)d_in[10], (const float*)d_in[11],
                                    (const float*)d_in[13]);

    k_output<<<NPIX/16, 128, 4928>>>((const float*)d_in[15],
                                     (const float*)d_in[16], (const float*)d_in[17],
                                     (const float*)d_in[19],
                                     (float*)d_out);
}

// round 17
// speedup vs baseline: 1.0973x; 1.0973x over previous
#include <cuda_runtime.h>

// ---------------------------------------------------------------------------
// SpatialRangeAttention — GB300 sm_103a
// ---------------------------------------------------------------------------

#define BB   2
#define CC   64
#define HH   112
#define WW   112
#define HWP  (HH*WW)      // 12544
#define NPIX (BB*HWP)     // 25088
#define N2   49

// Scratch
__device__ float g_spa_t[NPIX*CC];   // spatial transposed [pix][c]
__device__ float g_px_cm[NPIX*CC];   // range-projected, CHANNEL-major [b][c][hw]
__device__ float g_nrm[NPIX];        // per-pixel ||px||^2
__device__ float g_comb[NPIX*N2];    // bilateral / final weights [pix][n]

// Interleaved weight buffers (shared by all blocks; L1/L2-resident)
__device__ float2 g_w1r[64*32], g_w2r[64*32];   // range
__device__ float2 g_w1f[113*32], g_w2f[49*32];  // fixup (zero-padded o>=49)
__device__ float2 g_w1o[64*32], g_w2o[64*32];   // output

// 16-FMA block: weight pair a=(w[o],w[o+32]) times 8 pixel x-values
#define ACC16(a, xa, xb)                              \
    y0[0]+=a.x*xa.x; y1[0]+=a.y*xa.x;                 \
    y0[1]+=a.x*xa.y; y1[1]+=a.y*xa.y;                 \
    y0[2]+=a.x*xa.z; y1[2]+=a.y*xa.z;                 \
    y0[3]+=a.x*xa.w; y1[3]+=a.y*xa.w;                 \
    y0[4]+=a.x*xb.x; y1[4]+=a.y*xb.x;                 \
    y0[5]+=a.x*xb.y; y1[5]+=a.y*xb.y;                 \
    y0[6]+=a.x*xb.z; y1[6]+=a.y*xb.z;                 \
    y0[7]+=a.x*xb.w; y1[7]+=a.y*xb.w;

// 8-FMA block: weight pair times 4 pixel x-values
#define ACC8(a, xa)                                   \
    y0[0]+=a.x*xa.x; y1[0]+=a.y*xa.x;                 \
    y0[1]+=a.x*xa.y; y1[1]+=a.y*xa.y;                 \
    y0[2]+=a.x*xa.z; y1[2]+=a.y*xa.z;                 \
    y0[3]+=a.x*xa.w; y1[3]+=a.y*xa.w;

// ---------------------------------------------------------------------------
// K-1: prep — interleave all conv weights into global float2 buffers
// ---------------------------------------------------------------------------
__global__ __launch_bounds__(256) void k_prep(
    const float* __restrict__ rw1, const float* __restrict__ rw2,
    const float* __restrict__ fw1, const float* __restrict__ fw2,
    const float* __restrict__ ow1, const float* __restrict__ ow2)
{
    int i = blockIdx.x * 256 + threadIdx.x;
    if (i < 2048) {
        int c = i >> 5, l = i & 31;
        g_w1r[i] = make_float2(rw1[l*64 + c], rw1[(l+32)*64 + c]);
        g_w2r[i] = make_float2(rw2[l*64 + c], rw2[(l+32)*64 + c]);
        g_w1o[i] = make_float2(ow1[l*64 + c], ow1[(l+32)*64 + c]);
        g_w2o[i] = make_float2(ow2[l*64 + c], ow2[(l+32)*64 + c]);
    }
    if (i < 113*32) {
        int j = i >> 5, l = i & 31;
        g_w1f[i] = make_float2((l    < N2) ? fw1[l*113 + j]      : 0.f,
                               (l+32 < N2) ? fw1[(l+32)*113 + j] : 0.f);
    }
    if (i < 49*32) {
        int j = i >> 5, l = i & 31;
        g_w2f[i] = make_float2((l    < N2) ? fw2[l*49 + j]      : 0.f,
                               (l+32 < N2) ? fw2[(l+32)*49 + j] : 0.f);
    }
}

// ---------------------------------------------------------------------------
// K0: transpose spatial input [B,C,HW] -> [B*HW, C]
// ---------------------------------------------------------------------------
__global__ __launch_bounds__(256) void k_transpose(const float* __restrict__ spa)
{
    __shared__ float t1[32][33];
    int b  = blockIdx.z;
    int c0 = blockIdx.y * 32;
    int p0 = blockIdx.x * 32;
    int tx = threadIdx.x, ty = threadIdx.y;
    #pragma unroll
    for (int i = ty; i < 32; i += 8)
        t1[i][tx] = spa[(b*CC + c0 + i)*HWP + p0 + tx];
    __syncthreads();
    #pragma unroll
    for (int i = ty; i < 32; i += 8)
        g_spa_t[(b*HWP + p0 + i)*CC + c0 + tx] = t1[tx][i];
}

// ---------------------------------------------------------------------------
// K1: range_proj. 8 px/warp, 16 accumulators, weights via LDG.
// 128 threads, grid NPIX/32 = 784 -> 21 warps/SM.   (R14-exact)
// ---------------------------------------------------------------------------
__global__ __launch_bounds__(128, 8) void k_range(
    const float* __restrict__ sem,
    const float* __restrict__ b1, const float* __restrict__ g,
    const float* __restrict__ be, const float* __restrict__ b2)
{
    extern __shared__ float sm[];
    float* xs = sm;                          // [4 warps][64 rows][8 px]
    int tid = threadIdx.x, lane = tid & 31, w = tid >> 5;

    float b1_0 = b1[lane], b1_1 = b1[lane+32];
    float g_0  = g[lane],  g_1  = g[lane+32];
    float be_0 = be[lane], be_1 = be[lane+32];
    float b2_0 = b2[lane], b2_1 = b2[lane+32];

    int pbase = blockIdx.x * 32 + w * 8;
    int bI = pbase / HWP, ppb = pbase % HWP;
    float* xw = xs + w * 512;

    {
        int q = lane & 7, grp = lane >> 3;
        const float* semb = sem + (size_t)bI*CC*HWP + ppb + q;
        #pragma unroll 4
        for (int i = 0; i < 16; i++) {
            int c = grp*16 + i;
            xw[c*8 + q] = semb[(size_t)c*HWP];
        }
    }
    __syncwarp();

    float y0[8], y1[8];
    #pragma unroll
    for (int q = 0; q < 8; q++) { y0[q] = b1_0; y1[q] = b1_1; }

    #pragma unroll 4
    for (int c = 0; c < 64; c++) {
        float2 a = __ldg(&g_w1r[c*32 + lane]);
        float4 xa = *(const float4*)(xw + c*8);
        float4 xb = *(const float4*)(xw + c*8 + 4);
        ACC16(a, xa, xb)
    }

    {
        float h0[8], h1[8];
        #pragma unroll
        for (int q = 0; q < 8; q++) {
            float s = y0[q] + y1[q];
            float t = y0[q]*y0[q] + y1[q]*y1[q];
            #pragma unroll
            for (int o = 16; o; o >>= 1) {
                s += __shfl_xor_sync(0xffffffffu, s, o);
                t += __shfl_xor_sync(0xffffffffu, t, o);
            }
            float mean = s * (1.f/64.f);
            float rstd = rsqrtf(t * (1.f/64.f) - mean*mean + 1e-6f);
            float a0 = g_0 * (y0[q]-mean) * rstd + be_0;
            float a1 = g_1 * (y1[q]-mean) * rstd + be_1;
            h0[q] = a0 / (1.f + __expf(-a0));
            h1[q] = a1 / (1.f + __expf(-a1));
        }
        __syncwarp();
        *(float4*)&xw[lane*8]          = make_float4(h0[0],h0[1],h0[2],h0[3]);
        *(float4*)&xw[lane*8 + 4]      = make_float4(h0[4],h0[5],h0[6],h0[7]);
        *(float4*)&xw[(lane+32)*8]     = make_float4(h1[0],h1[1],h1[2],h1[3]);
        *(float4*)&xw[(lane+32)*8 + 4] = make_float4(h1[4],h1[5],h1[6],h1[7]);
        __syncwarp();
    }

    #pragma unroll
    for (int q = 0; q < 8; q++) { y0[q] = b2_0; y1[q] = b2_1; }
    #pragma unroll 4
    for (int c = 0; c < 64; c++) {
        float2 a = __ldg(&g_w2r[c*32 + lane]);
        float4 xa = *(const float4*)(xw + c*8);
        float4 xb = *(const float4*)(xw + c*8 + 4);
        ACC16(a, xa, xb)
    }

    #pragma unroll
    for (int q = 0; q < 8; q++) {
        float t = y0[q]*y0[q] + y1[q]*y1[q];
        #pragma unroll
        for (int o = 16; o; o >>= 1) t += __shfl_xor_sync(0xffffffffu, t, o);
        if (lane == 0) g_nrm[pbase + q] = t;
    }
    {
        float* d0 = &g_px_cm[(size_t)(bI*CC + lane)*HWP + ppb];
        *(float4*)d0       = make_float4(y0[0],y0[1],y0[2],y0[3]);
        *(float4*)(d0 + 4) = make_float4(y0[4],y0[5],y0[6],y0[7]);
        float* d1 = &g_px_cm[(size_t)(bI*CC + lane + 32)*HWP + ppb];
        *(float4*)d1       = make_float4(y1[0],y1[1],y1[2],y1[3]);
        *(float4*)(d1 + 4) = make_float4(y1[4],y1[5],y1[6],y1[7]);
    }
}

// ---------------------------------------------------------------------------
// K2: bilateral (R9-exact): dist2 = |n|^2+|c|^2-2dot. Warp = (32 pixels, dy).
// ---------------------------------------------------------------------------
__global__ __launch_bounds__(256) void k_bilateral(const float* __restrict__ sigma)
{
    int wid  = (blockIdx.x << 3) + (threadIdx.x >> 5);
    int lane = threadIdx.x & 31;
    int gpix = wid / 7;
    int dyi  = wid - gpix*7;
    int dy   = dyi - 3;

    int p  = (gpix << 5) + lane;
    int b  = p / HWP, pp = p % HWP, yy = pp / WW, xx = pp % WW;
    int ny = yy + dy;
    bool rowok = ((unsigned)ny < HH);
    int nrow = (rowok ? ny : yy) * WW;

    const float* base = g_px_cm + (size_t)b * (CC*HWP);

    int off[7]; unsigned okm = 0;
    #pragma unroll
    for (int i = 0; i < 7; i++) {
        int nx = xx + i - 3;
        bool o = rowok & ((unsigned)nx < WW);
        okm |= (o ? 1u : 0u) << i;
        off[i] = nrow + (o ? nx : xx);
    }

    float acc[7] = {0.f,0.f,0.f,0.f,0.f,0.f,0.f};
    #pragma unroll 4
    for (int c = 0; c < CC; c++) {
        const float* rc = base + c*HWP;
        float cv = rc[pp];
        #pragma unroll
        for (int i = 0; i < 7; i++) acc[i] += cv * rc[off[i]];
    }

    float nc = g_nrm[p];
    float sg = *sigma;
    float is2 = 0.5f / (sg*sg);
    float* outp = &g_comb[(size_t)p*N2 + dyi*7];
    const float* nrmb = &g_nrm[b*HWP];
    #pragma unroll
    for (int i = 0; i < 7; i++) {
        float res = 0.f;
        if ((okm >> i) & 1u) {
            float d2 = fmaxf(nrmb[off[i]] + nc - 2.f*acc[i], 0.f);
            float fdx = (float)(i - 3);
            res = __expf(-d2*(1.f/128.f) - ((float)(dy*dy) + fdx*fdx)*is2);
        }
        outp[i] = res;
    }
}

// ---------------------------------------------------------------------------
// K3a: fixup. 8 px/warp, 16 accumulators, weights via LDG.  (R14-exact)
// ---------------------------------------------------------------------------
__global__ __launch_bounds__(128, 8) void k_fixup(
    const float* __restrict__ sem,
    const float* __restrict__ b1, const float* __restrict__ g,
    const float* __restrict__ be, const float* __restrict__ b2)
{
    extern __shared__ float sm[];
    float* xs = sm;                          // [4 warps][113][8]
    int tid = threadIdx.x, lane = tid & 31, w = tid >> 5;

    const bool has2 = (lane + 32) < N2;
    float b1_0 = (lane < N2) ? b1[lane] : 0.f;
    float b1_1 = has2 ? b1[lane+32] : 0.f;
    float g_0  = (lane < N2) ? g[lane]  : 0.f;
    float g_1  = has2 ? g[lane+32]  : 0.f;
    float be_0 = (lane < N2) ? be[lane] : 0.f;
    float be_1 = has2 ? be[lane+32] : 0.f;
    float b2_0 = (lane < N2) ? b2[lane] : 0.f;
    float b2_1 = has2 ? b2[lane+32] : 0.f;

    int pbase = blockIdx.x * 32 + w * 8;
    int bI = pbase / HWP, ppb = pbase % HWP;
    float* xw = xs + w * 904;

    {
        int q = lane & 7, grp = lane >> 3;
        const float* combp = g_comb + (size_t)(pbase + q)*N2;
        const float* semb  = sem + (size_t)bI*CC*HWP + ppb + q;
        int j0 = grp * 29;
        int j1 = (grp == 3) ? 113 : j0 + 29;
        for (int j = j0; j < j1; j++) {
            float v = (j < N2) ? combp[j] : semb[(size_t)(j - N2)*HWP];
            xw[j*8 + q] = v;
        }
    }
    __syncwarp();

    float y0[8], y1[8];
    #pragma unroll
    for (int q = 0; q < 8; q++) { y0[q] = b1_0; y1[q] = b1_1; }

    #pragma unroll 4
    for (int j = 0; j < 113; j++) {
        float2 a = __ldg(&g_w1f[j*32 + lane]);
        float4 xa = *(const float4*)(xw + j*8);
        float4 xb = *(const float4*)(xw + j*8 + 4);
        ACC16(a, xa, xb)
    }

    {
        float h0[8], h1[8];
        #pragma unroll
        for (int q = 0; q < 8; q++) {
            float s = y0[q] + (has2 ? y1[q] : 0.f);
            float t = y0[q]*y0[q] + (has2 ? y1[q]*y1[q] : 0.f);
            #pragma unroll
            for (int o = 16; o; o >>= 1) {
                s += __shfl_xor_sync(0xffffffffu, s, o);
                t += __shfl_xor_sync(0xffffffffu, t, o);
            }
            float mean = s * (1.f/49.f);
            float rstd = rsqrtf(t * (1.f/49.f) - mean*mean + 1e-6f);
            float a0 = g_0 * (y0[q]-mean) * rstd + be_0;
            float a1 = g_1 * (y1[q]-mean) * rstd + be_1;
            h0[q] = a0 / (1.f + __expf(-a0));
            h1[q] = a1 / (1.f + __expf(-a1));
        }
        __syncwarp();
        *(float4*)&xw[lane*8]     = make_float4(h0[0],h0[1],h0[2],h0[3]);
        *(float4*)&xw[lane*8 + 4] = make_float4(h0[4],h0[5],h0[6],h0[7]);
        if (has2) {
            *(float4*)&xw[(lane+32)*8]     = make_float4(h1[0],h1[1],h1[2],h1[3]);
            *(float4*)&xw[(lane+32)*8 + 4] = make_float4(h1[4],h1[5],h1[6],h1[7]);
        }
        __syncwarp();
    }

    #pragma unroll
    for (int q = 0; q < 8; q++) { y0[q] = b2_0; y1[q] = b2_1; }
    #pragma unroll 4
    for (int j = 0; j < 49; j++) {
        float2 a = __ldg(&g_w2f[j*32 + lane]);
        float4 xa = *(const float4*)(xw + j*8);
        float4 xb = *(const float4*)(xw + j*8 + 4);
        ACC16(a, xa, xb)
    }

    #pragma unroll
    for (int q = 0; q < 8; q++) {
        int p = pbase + q;
        float cb0 = g_comb[(size_t)p*N2 + lane];
        float cb1 = has2 ? g_comb[(size_t)p*N2 + lane + 32] : 0.f;
        float wv0 = cb0 * (1.f + 1.f/(1.f + __expf(-y0[q])));
        float wv1 = has2 ? cb1 * (1.f + 1.f/(1.f + __expf(-y1[q]))) : 0.f;
        float ss = wv0 + wv1;
        #pragma unroll
        for (int o = 16; o; o >>= 1) ss += __shfl_xor_sync(0xffffffffu, ss, o);
        float inv = 1.f / (ss + 1e-7f);
        g_comb[(size_t)p*N2 + lane] = wv0 * inv;
        if (has2) g_comb[(size_t)p*N2 + lane + 32] = wv1 * inv;
    }
}

// ---------------------------------------------------------------------------
// K3b: weighted neighborhood reduction + output_proj, weights via LDG.
// 4 px/warp, 128 threads, grid NPIX/16 (R14 shape) + interior fast path.
// ---------------------------------------------------------------------------
__global__ __launch_bounds__(128, 10) void k_output(
    const float* __restrict__ b1, const float* __restrict__ g,
    const float* __restrict__ be, const float* __restrict__ b2,
    float* __restrict__ out)
{
    extern __shared__ float sm[];
    float* wsb = sm;                        // [4][52]
    float* os  = sm + 208;                  // [4 warps][64][4]
    int tid = threadIdx.x, lane = tid & 31, w = tid >> 5;

    float b1_0 = b1[lane], b1_1 = b1[lane+32];
    float g_0  = g[lane],  g_1  = g[lane+32];
    float be_0 = be[lane], be_1 = be[lane+32];
    float b2_0 = b2[lane], b2_1 = b2[lane+32];

    int pbase = blockIdx.x * 16 + w * 4;
    int bI = pbase / HWP, ppb = pbase % HWP;
    float* ow   = os  + w * 256;
    float* wrow = wsb + w * 52;

    // Gather: lane owns channels (2*lane, 2*lane+1)
    {
        float a0[4], a1[4];
        #pragma unroll
        for (int q = 0; q < 4; q++) {
            int pp = ppb + q;
            int yy = pp / WW, xx = pp % WW;

            for (int n = lane; n < N2; n += 32) wrow[n] = g_comb[(size_t)(pbase+q)*N2 + n];
            __syncwarp();

            float s0 = 0.f, s1 = 0.f;
            if (yy >= 3 && yy < HH-3 && xx >= 3 && xx < WW-3) {
                // interior fast path: no clamps, pointer-walk
                const float* rp0 = &g_spa_t[(size_t)(bI*HWP + (yy-3)*WW + (xx-3))*CC + lane*2];
                int n = 0;
                #pragma unroll
                for (int dy = 0; dy < 7; dy++) {
                    const float* rp = rp0 + (size_t)dy*WW*CC;
                    #pragma unroll
                    for (int dx = 0; dx < 7; dx++, n++) {
                        float wv = wrow[n];
                        float2 sv = *(const float2*)(rp + dx*CC);
                        s0 += sv.x * wv;
                        s1 += sv.y * wv;
                    }
                }
            } else {
                int n = 0;
                #pragma unroll
                for (int dy = -3; dy <= 3; dy++) {
                    int ny = min(max(yy + dy, 0), HH-1);
                    const float* rbase = &g_spa_t[(size_t)(bI*HWP + ny*WW)*CC + lane*2];
                    #pragma unroll
                    for (int dx = -3; dx <= 3; dx++, n++) {
                        int nx = min(max(xx + dx, 0), WW-1);
                        float wv = wrow[n];              // 0 for OOB neighbors
                        float2 sv = *(const float2*)(rbase + nx*CC);
                        s0 += sv.x * wv;
                        s1 += sv.y * wv;
                    }
                }
            }
            a0[q] = s0; a1[q] = s1;
            __syncwarp();
        }
        *(float4*)&ow[(lane*2)*4]   = make_float4(a0[0],a0[1],a0[2],a0[3]);
        *(float4*)&ow[(lane*2+1)*4] = make_float4(a1[0],a1[1],a1[2],a1[3]);
        __syncwarp();
    }

    float y0[4], y1[4];
    #pragma unroll
    for (int q = 0; q < 4; q++) { y0[q] = b1_0; y1[q] = b1_1; }
    #pragma unroll 4
    for (int c = 0; c < 64; c++) {
        float2 a = __ldg(&g_w1o[c*32 + lane]);
        float4 xa = *(const float4*)(ow + c*4);
        ACC8(a, xa)
    }

    {
        float h0[4], h1[4];
        #pragma unroll
        for (int q = 0; q < 4; q++) {
            float s = y0[q] + y1[q];
            float t = y0[q]*y0[q] + y1[q]*y1[q];
            #pragma unroll
            for (int o = 16; o; o >>= 1) {
                s += __shfl_xor_sync(0xffffffffu, s, o);
                t += __shfl_xor_sync(0xffffffffu, t, o);
            }
            float mean = s * (1.f/64.f);
            float rstd = rsqrtf(t * (1.f/64.f) - mean*mean + 1e-6f);
            h0[q] = g_0 * (y0[q]-mean) * rstd + be_0;
            h1[q] = g_1 * (y1[q]-mean) * rstd + be_1;
        }
        __syncwarp();
        *(float4*)&ow[lane*4]      = make_float4(h0[0],h0[1],h0[2],h0[3]);
        *(float4*)&ow[(lane+32)*4] = make_float4(h1[0],h1[1],h1[2],h1[3]);
        __syncwarp();
    }

    #pragma unroll
    for (int q = 0; q < 4; q++) { y0[q] = b2_0; y1[q] = b2_1; }
    #pragma unroll 4
    for (int c = 0; c < 64; c++) {
        float2 a = __ldg(&g_w2o[c*32 + lane]);
        float4 xa = *(const float4*)(ow + c*4);
        ACC8(a, xa)
    }

    {
        float* d0 = &out[(size_t)(bI*CC + lane)*HWP + ppb];
        *(float4*)d0 = make_float4(y0[0],y0[1],y0[2],y0[3]);
        float* d1 = &out[(size_t)(bI*CC + lane + 32)*HWP + ppb];
        *(float4*)d1 = make_float4(y1[0],y1[1],y1[2],y1[3]);
    }
}

// ---------------------------------------------------------------------------
extern "C" void kernel_launch(void* const* d_in, const int* in_sizes, int n_in,
                              void* d_out, int out_size)
{
    const float* spa = (const float*)d_in[0];
    const float* sem = (const float*)d_in[1];

    static bool attr_set = false;
    if (!attr_set) {
        cudaFuncSetAttribute(k_range,  cudaFuncAttributeMaxDynamicSharedMemorySize, 8192);
        cudaFuncSetAttribute(k_fixup,  cudaFuncAttributeMaxDynamicSharedMemorySize, 14464);
        cudaFuncSetAttribute(k_output, cudaFuncAttributeMaxDynamicSharedMemorySize, 4928);
        attr_set = true;
    }

    k_prep<<<15, 256>>>((const float*)d_in[2], (const float*)d_in[6],
                        (const float*)d_in[8], (const float*)d_in[12],
                        (const float*)d_in[14], (const float*)d_in[18]);

    dim3 tg(HWP/32, CC/32, BB), tb(32, 8);
    k_transpose<<<tg, tb>>>(spa);

    k_range<<<NPIX/32, 128, 8192>>>(sem,
                                    (const float*)d_in[3],
                                    (const float*)d_in[4], (const float*)d_in[5],
                                    (const float*)d_in[7]);

    // warps = (NPIX/32) * 7 = 5488 ; 8 warps/block -> 686 blocks
    k_bilateral<<<686, 256>>>((const float*)d_in[20]);

    k_fixup<<<NPIX/32, 128, 14464>>>(sem,
                                     (const float*)d_in[9],
                                     (const float*)d_in[10], (const float*)d_in[11],
                                     (const float*)d_in[13]);

    k_output<<<NPIX/16, 128, 4928>>>((const float*)d_in[15],
                                     (const float*)d_in[16], (const float*)d_in[17],
                                     (const float*)d_in[19],
                                     (float*)d_out);
}